// round 5
// baseline (speedup 1.0000x reference)
#include <cuda_runtime.h>
#include <cstdint>

#define CN0  400000
#define CN1  40000
#define CN2  4000
#define CIN  128
#define CHID 256
#define COUT 64
#define CE1  640000
#define CE2  64000

// ---- scratch (device globals: no allocation allowed) ----
__device__ float g_agg1[CN1 * CIN];    // mean-aggregated layer-1 messages
__device__ float g_h   [CN1 * CHID];   // relu'd layer-1 output
__device__ float g_agg2[CN2 * CHID];
__device__ int   g_cnt1[CN1];          // histogram, then fill cursors
__device__ int   g_off1[CN1 + 1];
__device__ int   g_csr1[CE1];          // src ids grouped by dst
__device__ int   g_cnt2[CN2];
__device__ int   g_off2[CN2 + 1];
__device__ int   g_csr2[CE2];

// ---------------------------------------------------------------------------
// zero the CSR counters
// ---------------------------------------------------------------------------
__global__ void k_zero() {
    int i = blockIdx.x * blockDim.x + threadIdx.x;
    int stride = gridDim.x * blockDim.x;
    for (int j = i; j < CN1; j += stride) g_cnt1[j] = 0;
    for (int j = i; j < CN2; j += stride) g_cnt2[j] = 0;
}

// ---------------------------------------------------------------------------
// CSR build: histogram -> scan (single block) -> ticket fill
// (device globals are referenced INSIDE device code only)
// ---------------------------------------------------------------------------
__global__ void k_count1(const int* __restrict__ dst, int E) {
    int i = blockIdx.x * blockDim.x + threadIdx.x;
    if (i < E) atomicAdd(g_cnt1 + dst[i], 1);
}
__global__ void k_count2(const int* __restrict__ dst, int E) {
    int i = blockIdx.x * blockDim.x + threadIdx.x;
    if (i < E) atomicAdd(g_cnt2 + dst[i], 1);
}

__device__ __forceinline__ void scan_impl(int* cnt, int* off, int n) {
    __shared__ int ps[1024];
    const int t = threadIdx.x;
    const int chunk = (n + 1023) >> 10;
    const int beg = t * chunk;
    const int end = min(beg + chunk, n);
    int s = 0;
    for (int i = beg; i < end; i++) s += cnt[i];
    ps[t] = s;
    __syncthreads();
    #pragma unroll
    for (int d = 1; d < 1024; d <<= 1) {
        int v = (t >= d) ? ps[t - d] : 0;
        __syncthreads();
        ps[t] += v;
        __syncthreads();
    }
    int run = (t == 0) ? 0 : ps[t - 1];
    for (int i = beg; i < end; i++) {
        int c = cnt[i];
        off[i] = run;
        run += c;
        cnt[i] = 0;                    // reuse as fill cursor
    }
    if (t == 1023) off[n] = ps[1023];
}
__global__ void __launch_bounds__(1024) k_scan1() { scan_impl(g_cnt1, g_off1, CN1); }
__global__ void __launch_bounds__(1024) k_scan2() { scan_impl(g_cnt2, g_off2, CN2); }

__global__ void k_fill1(const int* __restrict__ src, const int* __restrict__ dst, int E) {
    int i = blockIdx.x * blockDim.x + threadIdx.x;
    if (i >= E) return;
    int d = dst[i];
    int pos = atomicAdd(g_cnt1 + d, 1);
    g_csr1[g_off1[d] + pos] = src[i];
}
__global__ void k_fill2(const int* __restrict__ src, const int* __restrict__ dst, int E) {
    int i = blockIdx.x * blockDim.x + threadIdx.x;
    if (i >= E) return;
    int d = dst[i];
    int pos = atomicAdd(g_cnt2 + d, 1);
    g_csr2[g_off2[d] + pos] = src[i];
}

// ---------------------------------------------------------------------------
// layer-1 gather-mean: warp per dst row, 128 floats = 32 lanes x float4
// ---------------------------------------------------------------------------
__global__ void __launch_bounds__(256) k_gather1(const float* __restrict__ x) {
    int w = (blockIdx.x * blockDim.x + threadIdx.x) >> 5;
    if (w >= CN1) return;
    int lane = threadIdx.x & 31;
    int e0 = g_off1[w], e1 = g_off1[w + 1];
    float4 acc = make_float4(0.f, 0.f, 0.f, 0.f);
    int i = e0;
    for (; i + 3 < e1; i += 4) {
        int s0 = g_csr1[i], s1 = g_csr1[i + 1], s2 = g_csr1[i + 2], s3 = g_csr1[i + 3];
        float4 v0 = ((const float4*)(x + (size_t)s0 * CIN))[lane];
        float4 v1 = ((const float4*)(x + (size_t)s1 * CIN))[lane];
        float4 v2 = ((const float4*)(x + (size_t)s2 * CIN))[lane];
        float4 v3 = ((const float4*)(x + (size_t)s3 * CIN))[lane];
        acc.x += v0.x + v1.x + v2.x + v3.x;
        acc.y += v0.y + v1.y + v2.y + v3.y;
        acc.z += v0.z + v1.z + v2.z + v3.z;
        acc.w += v0.w + v1.w + v2.w + v3.w;
    }
    for (; i < e1; i++) {
        int s = g_csr1[i];
        float4 v = ((const float4*)(x + (size_t)s * CIN))[lane];
        acc.x += v.x; acc.y += v.y; acc.z += v.z; acc.w += v.w;
    }
    float id = 1.0f / fmaxf((float)(e1 - e0), 1.0f);
    acc.x *= id; acc.y *= id; acc.z *= id; acc.w *= id;
    ((float4*)(g_agg1 + (size_t)w * CIN))[lane] = acc;
}

// ---------------------------------------------------------------------------
// layer-2 gather-mean: warp per dst row, 256 floats = 2 x (32 lanes x float4)
// ---------------------------------------------------------------------------
__global__ void __launch_bounds__(256) k_gather2() {
    int w = (blockIdx.x * blockDim.x + threadIdx.x) >> 5;
    if (w >= CN2) return;
    int lane = threadIdx.x & 31;
    int e0 = g_off2[w], e1 = g_off2[w + 1];
    float4 a0 = make_float4(0.f, 0.f, 0.f, 0.f);
    float4 a1 = a0;
    int i = e0;
    for (; i + 1 < e1; i += 2) {
        int s0 = g_csr2[i], s1 = g_csr2[i + 1];
        const float4* p0 = (const float4*)(g_h + (size_t)s0 * CHID);
        const float4* p1 = (const float4*)(g_h + (size_t)s1 * CHID);
        float4 u0 = p0[lane], u1 = p0[lane + 32];
        float4 v0 = p1[lane], v1 = p1[lane + 32];
        a0.x += u0.x + v0.x; a0.y += u0.y + v0.y; a0.z += u0.z + v0.z; a0.w += u0.w + v0.w;
        a1.x += u1.x + v1.x; a1.y += u1.y + v1.y; a1.z += u1.z + v1.z; a1.w += u1.w + v1.w;
    }
    for (; i < e1; i++) {
        const float4* p = (const float4*)(g_h + (size_t)g_csr2[i] * CHID);
        float4 u0 = p[lane], u1 = p[lane + 32];
        a0.x += u0.x; a0.y += u0.y; a0.z += u0.z; a0.w += u0.w;
        a1.x += u1.x; a1.y += u1.y; a1.z += u1.z; a1.w += u1.w;
    }
    float id = 1.0f / fmaxf((float)(e1 - e0), 1.0f);
    a0.x *= id; a0.y *= id; a0.z *= id; a0.w *= id;
    a1.x *= id; a1.y *= id; a1.z *= id; a1.w *= id;
    float4* ap = (float4*)(g_agg2 + (size_t)w * CHID);
    ap[lane] = a0;
    ap[lane + 32] = a1;
}

// ---------------------------------------------------------------------------
// tf32 helpers
// ---------------------------------------------------------------------------
__device__ __forceinline__ uint32_t f2tf(float v) {
    uint32_t r;
    asm("cvt.rna.tf32.f32 %0, %1;" : "=r"(r) : "f"(v));
    return r;
}

__device__ __forceinline__ void mma_tf32(float* c, const uint32_t* a, const uint32_t* b) {
    asm volatile(
        "mma.sync.aligned.m16n8k8.row.col.f32.tf32.tf32.f32 "
        "{%0,%1,%2,%3}, {%4,%5,%6,%7}, {%8,%9}, {%0,%1,%2,%3};"
        : "+f"(c[0]), "+f"(c[1]), "+f"(c[2]), "+f"(c[3])
        : "r"(a[0]), "r"(a[1]), "r"(a[2]), "r"(a[3]), "r"(b[0]), "r"(b[1]));
}

__device__ __forceinline__ uint32_t s2u(const void* p) {
    return (uint32_t)__cvta_generic_to_shared(p);
}

__device__ __forceinline__ void cp16(uint32_t dst, const void* src, int sz) {
    asm volatile("cp.async.cg.shared.global [%0], [%1], 16, %2;"
                 :: "r"(dst), "l"(src), "r"(sz));
}

// ---------------------------------------------------------------------------
// layer-1 fused GEMM (tf32, cp.async double-buffered):
//   h = relu([agg1 | x_root] @ [w_l1;w_r1] + b_l1)   (agg1 already mean'd)
// M=40000, K=256 (16 iters of BK=16; iters 0-7: agg1/wl, 8-15: x/wr), N=256.
// BM=BN=128, 256 thr, warp grid 4x2, warp tile 32x64.
// ---------------------------------------------------------------------------
__global__ void __launch_bounds__(256, 2) k_gemm1(const float* __restrict__ x,
                                                  const float* __restrict__ wl,
                                                  const float* __restrict__ wr,
                                                  const float* __restrict__ bias) {
    __shared__ float As[2][128][20];   // [m][k], stride 20: conflict-free frag loads
    __shared__ float Bs[2][16][132];   // [k][n], stride 132

    const int t = threadIdx.x;
    const int lane = t & 31, warp = t >> 5;
    const int warp_m = warp & 3;
    const int warp_n = warp >> 2;
    const int m0 = blockIdx.y * 128;
    const int n0 = blockIdx.x * 128;
    const int fr = lane >> 2;
    const int fc = lane & 3;

    const int a_row0 = t >> 2,         a_kq0 = (t & 3) * 4;
    const int a_row1 = (t + 256) >> 2, a_kq1 = a_kq0;
    const int b_k0   = t >> 5,         b_nq0 = (t & 31) * 4;
    const int b_k1   = (t + 256) >> 5, b_nq1 = b_nq0;

    float acc[2][8][4] = {};

    auto issue = [&](int it, int buf) {
        const int kk = (it & 7) * 16;
        const float* Abase = (it < 8) ? g_agg1 : x;
        const float* Bbase = (it < 8) ? wl : wr;
        {
            int gm = m0 + a_row0;
            int sz = 16, gmc = gm;
            if (gm >= CN1) { gmc = 0; sz = 0; }
            cp16(s2u(&As[buf][a_row0][a_kq0]),
                 Abase + (size_t)gmc * CIN + kk + a_kq0, sz);
        }
        {
            int gm = m0 + a_row1;
            int sz = 16, gmc = gm;
            if (gm >= CN1) { gmc = 0; sz = 0; }
            cp16(s2u(&As[buf][a_row1][a_kq1]),
                 Abase + (size_t)gmc * CIN + kk + a_kq1, sz);
        }
        cp16(s2u(&Bs[buf][b_k0][b_nq0]),
             Bbase + (size_t)(kk + b_k0) * CHID + n0 + b_nq0, 16);
        cp16(s2u(&Bs[buf][b_k1][b_nq1]),
             Bbase + (size_t)(kk + b_k1) * CHID + n0 + b_nq1, 16);
    };

    issue(0, 0);
    asm volatile("cp.async.commit_group;");

    for (int it = 0; it < 16; ++it) {
        const int buf = it & 1;
        if (it + 1 < 16) issue(it + 1, buf ^ 1);
        asm volatile("cp.async.commit_group;");
        asm volatile("cp.async.wait_group 1;");
        __syncthreads();

        const float (*A)[20] = As[buf];
        const float (*B)[132] = Bs[buf];
        #pragma unroll
        for (int ks = 0; ks < 2; ks++) {
            const int kb = ks * 8;
            uint32_t a[2][4], b[8][2];
            #pragma unroll
            for (int mt = 0; mt < 2; mt++) {
                int mr = warp_m * 32 + mt * 16 + fr;
                a[mt][0] = f2tf(A[mr][kb + fc]);
                a[mt][1] = f2tf(A[mr + 8][kb + fc]);
                a[mt][2] = f2tf(A[mr][kb + fc + 4]);
                a[mt][3] = f2tf(A[mr + 8][kb + fc + 4]);
            }
            #pragma unroll
            for (int nt = 0; nt < 8; nt++) {
                int nc = warp_n * 64 + nt * 8 + fr;
                b[nt][0] = f2tf(B[kb + fc][nc]);
                b[nt][1] = f2tf(B[kb + fc + 4][nc]);
            }
            #pragma unroll
            for (int mt = 0; mt < 2; mt++)
                #pragma unroll
                for (int nt = 0; nt < 8; nt++)
                    mma_tf32(acc[mt][nt], a[mt], b[nt]);
        }
        __syncthreads();
    }

    // ---- epilogue: bias + relu, write g_h ----
    #pragma unroll
    for (int mt = 0; mt < 2; mt++) {
        int gm = m0 + warp_m * 32 + mt * 16 + fr;
        #pragma unroll
        for (int nt = 0; nt < 8; nt++) {
            int gn = n0 + warp_n * 64 + nt * 8 + (fc << 1);
            float b0 = bias[gn], b1 = bias[gn + 1];
            if (gm < CN1) {
                float2 v = make_float2(fmaxf(acc[mt][nt][0] + b0, 0.f),
                                       fmaxf(acc[mt][nt][1] + b1, 0.f));
                *(float2*)(g_h + (size_t)gm * CHID + gn) = v;
            }
            if (gm + 8 < CN1) {
                float2 v = make_float2(fmaxf(acc[mt][nt][2] + b0, 0.f),
                                       fmaxf(acc[mt][nt][3] + b1, 0.f));
                *(float2*)(g_h + (size_t)(gm + 8) * CHID + gn) = v;
            }
        }
    }
}

// ---------------------------------------------------------------------------
// layer-2 fused GEMM + log_softmax.
// out = log_softmax([agg2 | h_root] @ [w_l2;w_r2] + b_l2)
// M=4000, K=512, N=64. Warp per row; lane owns cols {lane, lane+32}.
// ---------------------------------------------------------------------------
__global__ void __launch_bounds__(256) k_gemm2(const float* __restrict__ wl,
                                               const float* __restrict__ wr,
                                               const float* __restrict__ bias,
                                               float* __restrict__ out) {
    __shared__ float As[8][512];
    int warp = threadIdx.x >> 5, lane = threadIdx.x & 31;
    int m = blockIdx.x * 8 + warp;
    if (m >= CN2) return;
    #pragma unroll
    for (int i = 0; i < 8; i++)
        As[warp][lane + 32 * i] = g_agg2[(size_t)m * CHID + lane + 32 * i];
    #pragma unroll
    for (int i = 0; i < 8; i++)
        As[warp][CHID + lane + 32 * i] = g_h[(size_t)m * CHID + lane + 32 * i];
    __syncwarp();

    float acc0 = 0.f, acc1 = 0.f;
    const float* A = As[warp];
    #pragma unroll 8
    for (int k = 0; k < CHID; k++) {
        float a = A[k];
        acc0 += a * wl[k * COUT + lane];
        acc1 += a * wl[k * COUT + lane + 32];
    }
    #pragma unroll 8
    for (int k = 0; k < CHID; k++) {
        float a = A[CHID + k];
        acc0 += a * wr[k * COUT + lane];
        acc1 += a * wr[k * COUT + lane + 32];
    }
    acc0 += bias[lane];
    acc1 += bias[lane + 32];

    float mx = fmaxf(acc0, acc1);
    #pragma unroll
    for (int o = 16; o > 0; o >>= 1) mx = fmaxf(mx, __shfl_xor_sync(0xFFFFFFFFu, mx, o));
    float s = expf(acc0 - mx) + expf(acc1 - mx);
    #pragma unroll
    for (int o = 16; o > 0; o >>= 1) s += __shfl_xor_sync(0xFFFFFFFFu, s, o);
    float lse = mx + logf(s);
    out[(size_t)m * COUT + lane]      = acc0 - lse;
    out[(size_t)m * COUT + lane + 32] = acc1 - lse;
}

// ---------------------------------------------------------------------------
extern "C" void kernel_launch(void* const* d_in, const int* in_sizes, int n_in,
                              void* d_out, int out_size) {
    const float* x    = (const float*)d_in[0];
    const int*   src1 = (const int*)d_in[1];
    const int*   dst1 = (const int*)d_in[2];
    const int*   src2 = (const int*)d_in[3];
    const int*   dst2 = (const int*)d_in[4];
    const float* wl1  = (const float*)d_in[5];
    const float* bl1  = (const float*)d_in[6];
    const float* wr1  = (const float*)d_in[7];
    const float* wl2  = (const float*)d_in[8];
    const float* bl2  = (const float*)d_in[9];
    const float* wr2  = (const float*)d_in[10];
    int E1 = in_sizes[1];
    int E2 = in_sizes[3];

    k_zero<<<128, 256>>>();
    k_count1<<<(E1 + 255) / 256, 256>>>(dst1, E1);
    k_count2<<<(E2 + 255) / 256, 256>>>(dst2, E2);
    k_scan1<<<1, 1024>>>();
    k_scan2<<<1, 1024>>>();
    k_fill1<<<(E1 + 255) / 256, 256>>>(src1, dst1, E1);
    k_fill2<<<(E2 + 255) / 256, 256>>>(src2, dst2, E2);
    k_gather1<<<(CN1 * 32 + 255) / 256, 256>>>(x);
    k_gemm1<<<dim3(2, (CN1 + 127) / 128), 256>>>(x, wl1, wr1, bl1);
    k_gather2<<<(CN2 * 32 + 255) / 256, 256>>>();
    k_gemm2<<<(CN2 + 7) / 8, 256>>>(wl2, wr2, bl2, (float*)d_out);
}

// round 6
// speedup vs baseline: 1.2445x; 1.2445x over previous
#include <cuda_runtime.h>
#include <cstdint>

#define CN0  400000
#define CN1  40000
#define CN2  4000
#define CIN  128
#define CHID 256
#define COUT 64
#define CE1  640000
#define CE2  64000

// ---- scratch (device globals: no allocation allowed) ----
__device__ float g_agg1[CN1 * CIN];    // mean-aggregated layer-1 messages
__device__ float g_h   [CN1 * CHID];   // relu'd layer-1 output
__device__ float g_agg2[CN2 * CHID];
__device__ int   g_cnt1[CN1];          // histogram, then fill cursors
__device__ int   g_off1[CN1 + 1];
__device__ int   g_csr1[CE1];          // src ids grouped by dst
__device__ int   g_cnt2[CN2];
__device__ int   g_off2[CN2 + 1];
__device__ int   g_csr2[CE2];
__device__ int   g_bsum[64];           // block sums for the parallel scan

// ---------------------------------------------------------------------------
// zero the CSR counters
// ---------------------------------------------------------------------------
__global__ void k_zero() {
    int i = blockIdx.x * blockDim.x + threadIdx.x;
    int stride = gridDim.x * blockDim.x;
    for (int j = i; j < CN1; j += stride) g_cnt1[j] = 0;
    for (int j = i; j < CN2; j += stride) g_cnt2[j] = 0;
}

// ---------------------------------------------------------------------------
// CSR build: histogram -> 3-phase parallel scan -> ticket fill
// (device globals referenced INSIDE device code only; layer flag picks arrays)
// ---------------------------------------------------------------------------
__global__ void k_count1(const int* __restrict__ dst, int E) {
    int i = blockIdx.x * blockDim.x + threadIdx.x;
    if (i < E) atomicAdd(g_cnt1 + dst[i], 1);
}
__global__ void k_count2(const int* __restrict__ dst, int E) {
    int i = blockIdx.x * blockDim.x + threadIdx.x;
    if (i < E) atomicAdd(g_cnt2 + dst[i], 1);
}

// Phase A: per-block exclusive scan, emit block sum
__global__ void __launch_bounds__(1024) k_scan_a(int layer) {
    const int n   = layer ? CN2 : CN1;
    int* cnt = layer ? g_cnt2 : g_cnt1;
    int* off = layer ? g_off2 : g_off1;
    __shared__ int ps[1024];
    int t = threadIdx.x;
    int i = blockIdx.x * 1024 + t;
    int v = (i < n) ? cnt[i] : 0;
    ps[t] = v;
    __syncthreads();
    #pragma unroll
    for (int d = 1; d < 1024; d <<= 1) {
        int u = (t >= d) ? ps[t - d] : 0;
        __syncthreads();
        ps[t] += u;
        __syncthreads();
    }
    if (i < n) off[i] = ps[t] - v;          // block-local exclusive
    if (t == 1023) g_bsum[blockIdx.x] = ps[1023];
}

// Phase B: exclusive scan of block sums (<=40 of them)
__global__ void __launch_bounds__(64) k_scan_b(int nb) {
    __shared__ int ps[64];
    int t = threadIdx.x;
    int v = (t < nb) ? g_bsum[t] : 0;
    ps[t] = v;
    __syncthreads();
    #pragma unroll
    for (int d = 1; d < 64; d <<= 1) {
        int u = (t >= d) ? ps[t - d] : 0;
        __syncthreads();
        ps[t] += u;
        __syncthreads();
    }
    g_bsum[t] = ps[t] - v;                  // exclusive
}

// Phase C: add block prefix, reset cnt to 0 (fill cursor), set off[n]=E
__global__ void __launch_bounds__(1024) k_scan_c(int layer, int E) {
    const int n   = layer ? CN2 : CN1;
    int* cnt = layer ? g_cnt2 : g_cnt1;
    int* off = layer ? g_off2 : g_off1;
    int t = threadIdx.x;
    int i = blockIdx.x * 1024 + t;
    int add = g_bsum[blockIdx.x];
    if (i < n) { off[i] += add; cnt[i] = 0; }
    if (i == 0) off[n] = E;
}

__global__ void k_fill1(const int* __restrict__ src, const int* __restrict__ dst, int E) {
    int i = blockIdx.x * blockDim.x + threadIdx.x;
    if (i >= E) return;
    int d = dst[i];
    int pos = atomicAdd(g_cnt1 + d, 1);
    g_csr1[g_off1[d] + pos] = src[i];
}
__global__ void k_fill2(const int* __restrict__ src, const int* __restrict__ dst, int E) {
    int i = blockIdx.x * blockDim.x + threadIdx.x;
    if (i >= E) return;
    int d = dst[i];
    int pos = atomicAdd(g_cnt2 + d, 1);
    g_csr2[g_off2[d] + pos] = src[i];
}

// ---------------------------------------------------------------------------
// layer-1 gather-mean: warp per dst row, 128 floats = 32 lanes x float4
// ---------------------------------------------------------------------------
__global__ void __launch_bounds__(256) k_gather1(const float* __restrict__ x) {
    int w = (blockIdx.x * blockDim.x + threadIdx.x) >> 5;
    if (w >= CN1) return;
    int lane = threadIdx.x & 31;
    int e0 = g_off1[w], e1 = g_off1[w + 1];
    float4 acc = make_float4(0.f, 0.f, 0.f, 0.f);
    int i = e0;
    for (; i + 3 < e1; i += 4) {
        int s0 = g_csr1[i], s1 = g_csr1[i + 1], s2 = g_csr1[i + 2], s3 = g_csr1[i + 3];
        float4 v0 = ((const float4*)(x + (size_t)s0 * CIN))[lane];
        float4 v1 = ((const float4*)(x + (size_t)s1 * CIN))[lane];
        float4 v2 = ((const float4*)(x + (size_t)s2 * CIN))[lane];
        float4 v3 = ((const float4*)(x + (size_t)s3 * CIN))[lane];
        acc.x += v0.x + v1.x + v2.x + v3.x;
        acc.y += v0.y + v1.y + v2.y + v3.y;
        acc.z += v0.z + v1.z + v2.z + v3.z;
        acc.w += v0.w + v1.w + v2.w + v3.w;
    }
    for (; i < e1; i++) {
        int s = g_csr1[i];
        float4 v = ((const float4*)(x + (size_t)s * CIN))[lane];
        acc.x += v.x; acc.y += v.y; acc.z += v.z; acc.w += v.w;
    }
    float id = 1.0f / fmaxf((float)(e1 - e0), 1.0f);
    acc.x *= id; acc.y *= id; acc.z *= id; acc.w *= id;
    ((float4*)(g_agg1 + (size_t)w * CIN))[lane] = acc;
}

// ---------------------------------------------------------------------------
// layer-2 gather-mean: warp per dst row, 256 floats = 2 x (32 lanes x float4)
// ---------------------------------------------------------------------------
__global__ void __launch_bounds__(256) k_gather2() {
    int w = (blockIdx.x * blockDim.x + threadIdx.x) >> 5;
    if (w >= CN2) return;
    int lane = threadIdx.x & 31;
    int e0 = g_off2[w], e1 = g_off2[w + 1];
    float4 a0 = make_float4(0.f, 0.f, 0.f, 0.f);
    float4 a1 = a0;
    int i = e0;
    for (; i + 1 < e1; i += 2) {
        int s0 = g_csr2[i], s1 = g_csr2[i + 1];
        const float4* p0 = (const float4*)(g_h + (size_t)s0 * CHID);
        const float4* p1 = (const float4*)(g_h + (size_t)s1 * CHID);
        float4 u0 = p0[lane], u1 = p0[lane + 32];
        float4 v0 = p1[lane], v1 = p1[lane + 32];
        a0.x += u0.x + v0.x; a0.y += u0.y + v0.y; a0.z += u0.z + v0.z; a0.w += u0.w + v0.w;
        a1.x += u1.x + v1.x; a1.y += u1.y + v1.y; a1.z += u1.z + v1.z; a1.w += u1.w + v1.w;
    }
    for (; i < e1; i++) {
        const float4* p = (const float4*)(g_h + (size_t)g_csr2[i] * CHID);
        float4 u0 = p[lane], u1 = p[lane + 32];
        a0.x += u0.x; a0.y += u0.y; a0.z += u0.z; a0.w += u0.w;
        a1.x += u1.x; a1.y += u1.y; a1.z += u1.z; a1.w += u1.w;
    }
    float id = 1.0f / fmaxf((float)(e1 - e0), 1.0f);
    a0.x *= id; a0.y *= id; a0.z *= id; a0.w *= id;
    a1.x *= id; a1.y *= id; a1.z *= id; a1.w *= id;
    float4* ap = (float4*)(g_agg2 + (size_t)w * CHID);
    ap[lane] = a0;
    ap[lane + 32] = a1;
}

// ---------------------------------------------------------------------------
// tf32 helpers
// ---------------------------------------------------------------------------
__device__ __forceinline__ uint32_t f2tf(float v) {
    uint32_t r;
    asm("cvt.rna.tf32.f32 %0, %1;" : "=r"(r) : "f"(v));
    return r;
}

__device__ __forceinline__ void mma_tf32(float* c, const uint32_t* a, const uint32_t* b) {
    asm volatile(
        "mma.sync.aligned.m16n8k8.row.col.f32.tf32.tf32.f32 "
        "{%0,%1,%2,%3}, {%4,%5,%6,%7}, {%8,%9}, {%0,%1,%2,%3};"
        : "+f"(c[0]), "+f"(c[1]), "+f"(c[2]), "+f"(c[3])
        : "r"(a[0]), "r"(a[1]), "r"(a[2]), "r"(a[3]), "r"(b[0]), "r"(b[1]));
}

__device__ __forceinline__ uint32_t s2u(const void* p) {
    return (uint32_t)__cvta_generic_to_shared(p);
}

__device__ __forceinline__ void cp16(uint32_t dst, const void* src, int sz) {
    asm volatile("cp.async.cg.shared.global [%0], [%1], 16, %2;"
                 :: "r"(dst), "l"(src), "r"(sz));
}

// ---------------------------------------------------------------------------
// layer-1 fused GEMM (tf32, cp.async double-buffered):
//   h = relu([agg1 | x_root] @ [w_l1;w_r1] + b_l1)   (agg1 already mean'd)
// M=40000, K=256 (16 iters of BK=16; iters 0-7: agg1/wl, 8-15: x/wr), N=256.
// BM=BN=128, 256 thr, warp grid 4x2, warp tile 32x64.
// ---------------------------------------------------------------------------
__global__ void __launch_bounds__(256, 2) k_gemm1(const float* __restrict__ x,
                                                  const float* __restrict__ wl,
                                                  const float* __restrict__ wr,
                                                  const float* __restrict__ bias) {
    __shared__ float As[2][128][20];   // [m][k], stride 20: conflict-free frag loads
    __shared__ float Bs[2][16][132];   // [k][n], stride 132

    const int t = threadIdx.x;
    const int lane = t & 31, warp = t >> 5;
    const int warp_m = warp & 3;
    const int warp_n = warp >> 2;
    const int m0 = blockIdx.y * 128;
    const int n0 = blockIdx.x * 128;
    const int fr = lane >> 2;
    const int fc = lane & 3;

    const int a_row0 = t >> 2,         a_kq0 = (t & 3) * 4;
    const int a_row1 = (t + 256) >> 2, a_kq1 = a_kq0;
    const int b_k0   = t >> 5,         b_nq0 = (t & 31) * 4;
    const int b_k1   = (t + 256) >> 5, b_nq1 = b_nq0;

    float acc[2][8][4] = {};

    auto issue = [&](int it, int buf) {
        const int kk = (it & 7) * 16;
        const float* Abase = (it < 8) ? g_agg1 : x;
        const float* Bbase = (it < 8) ? wl : wr;
        {
            int gm = m0 + a_row0;
            int sz = 16, gmc = gm;
            if (gm >= CN1) { gmc = 0; sz = 0; }
            cp16(s2u(&As[buf][a_row0][a_kq0]),
                 Abase + (size_t)gmc * CIN + kk + a_kq0, sz);
        }
        {
            int gm = m0 + a_row1;
            int sz = 16, gmc = gm;
            if (gm >= CN1) { gmc = 0; sz = 0; }
            cp16(s2u(&As[buf][a_row1][a_kq1]),
                 Abase + (size_t)gmc * CIN + kk + a_kq1, sz);
        }
        cp16(s2u(&Bs[buf][b_k0][b_nq0]),
             Bbase + (size_t)(kk + b_k0) * CHID + n0 + b_nq0, 16);
        cp16(s2u(&Bs[buf][b_k1][b_nq1]),
             Bbase + (size_t)(kk + b_k1) * CHID + n0 + b_nq1, 16);
    };

    issue(0, 0);
    asm volatile("cp.async.commit_group;");

    for (int it = 0; it < 16; ++it) {
        const int buf = it & 1;
        if (it + 1 < 16) issue(it + 1, buf ^ 1);
        asm volatile("cp.async.commit_group;");
        asm volatile("cp.async.wait_group 1;");
        __syncthreads();

        const float (*A)[20] = As[buf];
        const float (*B)[132] = Bs[buf];
        #pragma unroll
        for (int ks = 0; ks < 2; ks++) {
            const int kb = ks * 8;
            uint32_t a[2][4], b[8][2];
            #pragma unroll
            for (int mt = 0; mt < 2; mt++) {
                int mr = warp_m * 32 + mt * 16 + fr;
                a[mt][0] = f2tf(A[mr][kb + fc]);
                a[mt][1] = f2tf(A[mr + 8][kb + fc]);
                a[mt][2] = f2tf(A[mr][kb + fc + 4]);
                a[mt][3] = f2tf(A[mr + 8][kb + fc + 4]);
            }
            #pragma unroll
            for (int nt = 0; nt < 8; nt++) {
                int nc = warp_n * 64 + nt * 8 + fr;
                b[nt][0] = f2tf(B[kb + fc][nc]);
                b[nt][1] = f2tf(B[kb + fc + 4][nc]);
            }
            #pragma unroll
            for (int mt = 0; mt < 2; mt++)
                #pragma unroll
                for (int nt = 0; nt < 8; nt++)
                    mma_tf32(acc[mt][nt], a[mt], b[nt]);
        }
        __syncthreads();
    }

    // ---- epilogue: bias + relu, write g_h ----
    #pragma unroll
    for (int mt = 0; mt < 2; mt++) {
        int gm = m0 + warp_m * 32 + mt * 16 + fr;
        #pragma unroll
        for (int nt = 0; nt < 8; nt++) {
            int gn = n0 + warp_n * 64 + nt * 8 + (fc << 1);
            float b0 = bias[gn], b1 = bias[gn + 1];
            if (gm < CN1) {
                float2 v = make_float2(fmaxf(acc[mt][nt][0] + b0, 0.f),
                                       fmaxf(acc[mt][nt][1] + b1, 0.f));
                *(float2*)(g_h + (size_t)gm * CHID + gn) = v;
            }
            if (gm + 8 < CN1) {
                float2 v = make_float2(fmaxf(acc[mt][nt][2] + b0, 0.f),
                                       fmaxf(acc[mt][nt][3] + b1, 0.f));
                *(float2*)(g_h + (size_t)(gm + 8) * CHID + gn) = v;
            }
        }
    }
}

// ---------------------------------------------------------------------------
// layer-2 fused GEMM + log_softmax.
// out = log_softmax([agg2 | h_root] @ [w_l2;w_r2] + b_l2)
// M=4000, K=512, N=64. Warp per row; lane owns cols {lane, lane+32}.
// ---------------------------------------------------------------------------
__global__ void __launch_bounds__(256) k_gemm2(const float* __restrict__ wl,
                                               const float* __restrict__ wr,
                                               const float* __restrict__ bias,
                                               float* __restrict__ out) {
    __shared__ float As[8][512];
    int warp = threadIdx.x >> 5, lane = threadIdx.x & 31;
    int m = blockIdx.x * 8 + warp;
    if (m >= CN2) return;
    #pragma unroll
    for (int i = 0; i < 8; i++)
        As[warp][lane + 32 * i] = g_agg2[(size_t)m * CHID + lane + 32 * i];
    #pragma unroll
    for (int i = 0; i < 8; i++)
        As[warp][CHID + lane + 32 * i] = g_h[(size_t)m * CHID + lane + 32 * i];
    __syncwarp();

    float acc0 = 0.f, acc1 = 0.f;
    const float* A = As[warp];
    #pragma unroll 8
    for (int k = 0; k < CHID; k++) {
        float a = A[k];
        acc0 += a * wl[k * COUT + lane];
        acc1 += a * wl[k * COUT + lane + 32];
    }
    #pragma unroll 8
    for (int k = 0; k < CHID; k++) {
        float a = A[CHID + k];
        acc0 += a * wr[k * COUT + lane];
        acc1 += a * wr[k * COUT + lane + 32];
    }
    acc0 += bias[lane];
    acc1 += bias[lane + 32];

    float mx = fmaxf(acc0, acc1);
    #pragma unroll
    for (int o = 16; o > 0; o >>= 1) mx = fmaxf(mx, __shfl_xor_sync(0xFFFFFFFFu, mx, o));
    float s = expf(acc0 - mx) + expf(acc1 - mx);
    #pragma unroll
    for (int o = 16; o > 0; o >>= 1) s += __shfl_xor_sync(0xFFFFFFFFu, s, o);
    float lse = mx + logf(s);
    out[(size_t)m * COUT + lane]      = acc0 - lse;
    out[(size_t)m * COUT + lane + 32] = acc1 - lse;
}

// ---------------------------------------------------------------------------
extern "C" void kernel_launch(void* const* d_in, const int* in_sizes, int n_in,
                              void* d_out, int out_size) {
    const float* x    = (const float*)d_in[0];
    const int*   src1 = (const int*)d_in[1];
    const int*   dst1 = (const int*)d_in[2];
    const int*   src2 = (const int*)d_in[3];
    const int*   dst2 = (const int*)d_in[4];
    const float* wl1  = (const float*)d_in[5];
    const float* bl1  = (const float*)d_in[6];
    const float* wr1  = (const float*)d_in[7];
    const float* wl2  = (const float*)d_in[8];
    const float* bl2  = (const float*)d_in[9];
    const float* wr2  = (const float*)d_in[10];
    int E1 = in_sizes[1];
    int E2 = in_sizes[3];

    const int nb1 = (CN1 + 1023) / 1024;   // 40
    const int nb2 = (CN2 + 1023) / 1024;   // 4

    k_zero<<<128, 256>>>();
    k_count1<<<(E1 + 255) / 256, 256>>>(dst1, E1);
    k_count2<<<(E2 + 255) / 256, 256>>>(dst2, E2);
    k_scan_a<<<nb1, 1024>>>(0);
    k_scan_b<<<1, 64>>>(nb1);
    k_scan_c<<<nb1, 1024>>>(0, E1);
    k_scan_a<<<nb2, 1024>>>(1);
    k_scan_b<<<1, 64>>>(nb2);
    k_scan_c<<<nb2, 1024>>>(1, E2);
    k_fill1<<<(E1 + 255) / 256, 256>>>(src1, dst1, E1);
    k_fill2<<<(E2 + 255) / 256, 256>>>(src2, dst2, E2);
    k_gather1<<<(CN1 * 32 + 255) / 256, 256>>>(x);
    k_gemm1<<<dim3(2, (CN1 + 127) / 128), 256>>>(x, wl1, wr1, bl1);
    k_gather2<<<(CN2 * 32 + 255) / 256, 256>>>();
    k_gemm2<<<(CN2 + 7) / 8, 256>>>(wl2, wr2, bl2, (float*)d_out);
}

// round 7
// speedup vs baseline: 1.3145x; 1.0563x over previous
#include <cuda_runtime.h>
#include <cstdint>

#define CN0  400000
#define CN1  40000
#define CN2  4000
#define CIN  128
#define CHID 256
#define COUT 64
#define CE1  640000
#define CE2  64000
#define NB1  40               // scan blocks layer1 (40960 >= 40000)
#define NB2  4                // scan blocks layer2 (4096 >= 4000)

// ---- scratch (device globals: no allocation allowed) ----
__device__ float g_agg1[CN1 * CIN];
__device__ float g_h   [CN1 * CHID];
__device__ float g_agg2[CN2 * CHID];
__device__ int   g_cnt1[CN1];
__device__ int   g_off1[CN1 + 1];
__device__ int   g_csr1[CE1];
__device__ int   g_cnt2[CN2];
__device__ int   g_off2[CN2 + 1];
__device__ int   g_csr2[CE2];
__device__ int   g_bsum[64];

// ---------------------------------------------------------------------------
__global__ void k_zero() {
    int i = blockIdx.x * blockDim.x + threadIdx.x;
    if (i < CN1) g_cnt1[i] = 0;
    if (i < CN2) g_cnt2[i] = 0;
}

// merged histogram for both layers
__global__ void k_count(const int* __restrict__ d1, const int* __restrict__ d2,
                        int E1, int E2) {
    int i = blockIdx.x * blockDim.x + threadIdx.x;
    if (i < E1) atomicAdd(g_cnt1 + d1[i], 1);
    else {
        int j = i - E1;
        if (j < E2) atomicAdd(g_cnt2 + d2[j], 1);
    }
}

// Phase A: per-block exclusive scan, emit block sum (blocks 0..39 L1, 40..43 L2)
__global__ void __launch_bounds__(1024) k_scan_a() {
    int b = blockIdx.x;
    int lay = (b >= NB1);
    int bb = lay ? b - NB1 : b;
    int n = lay ? CN2 : CN1;
    int* cnt = lay ? g_cnt2 : g_cnt1;
    int* off = lay ? g_off2 : g_off1;
    __shared__ int ps[1024];
    int t = threadIdx.x;
    int i = bb * 1024 + t;
    int v = (i < n) ? cnt[i] : 0;
    ps[t] = v;
    __syncthreads();
    #pragma unroll
    for (int d = 1; d < 1024; d <<= 1) {
        int u = (t >= d) ? ps[t - d] : 0;
        __syncthreads();
        ps[t] += u;
        __syncthreads();
    }
    if (i < n) off[i] = ps[t] - v;
    if (t == 1023) g_bsum[b] = ps[1023];
}

// Phase B: segmented exclusive scan of 44 block sums
__global__ void __launch_bounds__(64) k_scan_b() {
    __shared__ int ps[64];
    int t = threadIdx.x;
    int v = (t < NB1 + NB2) ? g_bsum[t] : 0;
    ps[t] = v;
    __syncthreads();
    #pragma unroll
    for (int d = 1; d < 64; d <<= 1) {
        int u = (t >= d) ? ps[t - d] : 0;
        __syncthreads();
        ps[t] += u;
        __syncthreads();
    }
    int seg0_total = ps[NB1 - 1];
    int base = (t >= NB1) ? seg0_total : 0;
    g_bsum[t] = ps[t] - v - base;
}

// Phase C: add block prefix, reset cnt (fill cursor), set off[n]=E
__global__ void __launch_bounds__(1024) k_scan_c(int E1, int E2) {
    int b = blockIdx.x;
    int lay = (b >= NB1);
    int bb = lay ? b - NB1 : b;
    int n = lay ? CN2 : CN1;
    int* cnt = lay ? g_cnt2 : g_cnt1;
    int* off = lay ? g_off2 : g_off1;
    int t = threadIdx.x;
    int i = bb * 1024 + t;
    int add = g_bsum[b];
    if (i < n) { off[i] += add; cnt[i] = 0; }
    if (i == 0) off[n] = lay ? E2 : E1;
}

// merged ticket fill for both layers
__global__ void k_fill(const int* __restrict__ s1, const int* __restrict__ d1,
                       const int* __restrict__ s2, const int* __restrict__ d2,
                       int E1, int E2) {
    int i = blockIdx.x * blockDim.x + threadIdx.x;
    if (i < E1) {
        int d = d1[i];
        int pos = atomicAdd(g_cnt1 + d, 1);
        g_csr1[g_off1[d] + pos] = s1[i];
    } else {
        int j = i - E1;
        if (j < E2) {
            int d = d2[j];
            int pos = atomicAdd(g_cnt2 + d, 1);
            g_csr2[g_off2[d] + pos] = s2[j];
        }
    }
}

// ---------------------------------------------------------------------------
// layer-1 gather-mean: warp per dst row, 128 floats = 32 lanes x float4
// ---------------------------------------------------------------------------
__global__ void __launch_bounds__(256) k_gather1(const float* __restrict__ x) {
    int w = (blockIdx.x * blockDim.x + threadIdx.x) >> 5;
    if (w >= CN1) return;
    int lane = threadIdx.x & 31;
    int e0 = g_off1[w], e1 = g_off1[w + 1];
    float4 acc = make_float4(0.f, 0.f, 0.f, 0.f);
    int i = e0;
    for (; i + 3 < e1; i += 4) {
        int s0 = g_csr1[i], s1 = g_csr1[i + 1], s2 = g_csr1[i + 2], s3 = g_csr1[i + 3];
        float4 v0 = ((const float4*)(x + (size_t)s0 * CIN))[lane];
        float4 v1 = ((const float4*)(x + (size_t)s1 * CIN))[lane];
        float4 v2 = ((const float4*)(x + (size_t)s2 * CIN))[lane];
        float4 v3 = ((const float4*)(x + (size_t)s3 * CIN))[lane];
        acc.x += v0.x + v1.x + v2.x + v3.x;
        acc.y += v0.y + v1.y + v2.y + v3.y;
        acc.z += v0.z + v1.z + v2.z + v3.z;
        acc.w += v0.w + v1.w + v2.w + v3.w;
    }
    for (; i < e1; i++) {
        int s = g_csr1[i];
        float4 v = ((const float4*)(x + (size_t)s * CIN))[lane];
        acc.x += v.x; acc.y += v.y; acc.z += v.z; acc.w += v.w;
    }
    float id = 1.0f / fmaxf((float)(e1 - e0), 1.0f);
    acc.x *= id; acc.y *= id; acc.z *= id; acc.w *= id;
    ((float4*)(g_agg1 + (size_t)w * CIN))[lane] = acc;
}

// ---------------------------------------------------------------------------
// layer-2 gather-mean
// ---------------------------------------------------------------------------
__global__ void __launch_bounds__(256) k_gather2() {
    int w = (blockIdx.x * blockDim.x + threadIdx.x) >> 5;
    if (w >= CN2) return;
    int lane = threadIdx.x & 31;
    int e0 = g_off2[w], e1 = g_off2[w + 1];
    float4 a0 = make_float4(0.f, 0.f, 0.f, 0.f);
    float4 a1 = a0;
    int i = e0;
    for (; i + 1 < e1; i += 2) {
        int s0 = g_csr2[i], s1 = g_csr2[i + 1];
        const float4* p0 = (const float4*)(g_h + (size_t)s0 * CHID);
        const float4* p1 = (const float4*)(g_h + (size_t)s1 * CHID);
        float4 u0 = p0[lane], u1 = p0[lane + 32];
        float4 v0 = p1[lane], v1 = p1[lane + 32];
        a0.x += u0.x + v0.x; a0.y += u0.y + v0.y; a0.z += u0.z + v0.z; a0.w += u0.w + v0.w;
        a1.x += u1.x + v1.x; a1.y += u1.y + v1.y; a1.z += u1.z + v1.z; a1.w += u1.w + v1.w;
    }
    for (; i < e1; i++) {
        const float4* p = (const float4*)(g_h + (size_t)g_csr2[i] * CHID);
        float4 u0 = p[lane], u1 = p[lane + 32];
        a0.x += u0.x; a0.y += u0.y; a0.z += u0.z; a0.w += u0.w;
        a1.x += u1.x; a1.y += u1.y; a1.z += u1.z; a1.w += u1.w;
    }
    float id = 1.0f / fmaxf((float)(e1 - e0), 1.0f);
    a0.x *= id; a0.y *= id; a0.z *= id; a0.w *= id;
    a1.x *= id; a1.y *= id; a1.z *= id; a1.w *= id;
    float4* ap = (float4*)(g_agg2 + (size_t)w * CHID);
    ap[lane] = a0;
    ap[lane + 32] = a1;
}

// ---------------------------------------------------------------------------
// tf32 helpers
// ---------------------------------------------------------------------------
__device__ __forceinline__ uint32_t f2tf(float v) {
    uint32_t r;
    asm("cvt.rna.tf32.f32 %0, %1;" : "=r"(r) : "f"(v));
    return r;
}

__device__ __forceinline__ void mma_tf32(float* c, const uint32_t* a, const uint32_t* b) {
    asm volatile(
        "mma.sync.aligned.m16n8k8.row.col.f32.tf32.tf32.f32 "
        "{%0,%1,%2,%3}, {%4,%5,%6,%7}, {%8,%9}, {%0,%1,%2,%3};"
        : "+f"(c[0]), "+f"(c[1]), "+f"(c[2]), "+f"(c[3])
        : "r"(a[0]), "r"(a[1]), "r"(a[2]), "r"(a[3]), "r"(b[0]), "r"(b[1]));
}

__device__ __forceinline__ uint32_t s2u(const void* p) {
    return (uint32_t)__cvta_generic_to_shared(p);
}

__device__ __forceinline__ void cp16(uint32_t dst, const void* src, int sz) {
    asm volatile("cp.async.cg.shared.global [%0], [%1], 16, %2;"
                 :: "r"(dst), "l"(src), "r"(sz));
}

// ---------------------------------------------------------------------------
// layer-1 fused GEMM (tf32, 3-stage cp.async pipeline, dynamic smem):
//   h = relu([agg1 | x_root] @ [w_l1;w_r1] + b_l1)
// M=40000, K=256 (16 iters BK=16; 0-7: agg1/wl, 8-15: x/wr), N=256.
// BM=BN=128, 256 thr, warp grid 4x2, warp tile 32x64.
// ---------------------------------------------------------------------------
#define A_ST 2560    /* 128*20 floats per stage */
#define B_ST 2176    /* 16*136 floats per stage */
#define SMEM_GEMM1 ((3 * (A_ST + B_ST)) * 4)

__global__ void __launch_bounds__(256, 2) k_gemm1(const float* __restrict__ x,
                                                  const float* __restrict__ wl,
                                                  const float* __restrict__ wr,
                                                  const float* __restrict__ bias) {
    extern __shared__ float sm[];
    float* Abuf = sm;                  // 3 stages of [128][20]
    float* Bbuf = sm + 3 * A_ST;       // 3 stages of [16][136]

    const int t = threadIdx.x;
    const int lane = t & 31, warp = t >> 5;
    const int warp_m = warp & 3;
    const int warp_n = warp >> 2;
    const int m0 = blockIdx.y * 128;
    const int n0 = blockIdx.x * 128;
    const int fr = lane >> 2;
    const int fc = lane & 3;

    const int a_row0 = t >> 2,         a_kq = (t & 3) * 4;
    const int a_row1 = (t + 256) >> 2;
    const int b_k0   = t >> 5,         b_nq = (t & 31) * 4;
    const int b_k1   = (t + 256) >> 5;

    float acc[2][8][4] = {};

    auto issue = [&](int it, int st) {
        const int kk = (it & 7) * 16;
        const float* Abase = (it < 8) ? g_agg1 : x;
        const float* Bbase = (it < 8) ? wl : wr;
        float* As = Abuf + st * A_ST;
        float* Bs = Bbuf + st * B_ST;
        {
            int gm = m0 + a_row0;
            int sz = 16, gmc = gm;
            if (gm >= CN1) { gmc = 0; sz = 0; }
            cp16(s2u(As + a_row0 * 20 + a_kq),
                 Abase + (size_t)gmc * CIN + kk + a_kq, sz);
        }
        {
            int gm = m0 + a_row1;
            int sz = 16, gmc = gm;
            if (gm >= CN1) { gmc = 0; sz = 0; }
            cp16(s2u(As + a_row1 * 20 + a_kq),
                 Abase + (size_t)gmc * CIN + kk + a_kq, sz);
        }
        cp16(s2u(Bs + b_k0 * 136 + b_nq),
             Bbase + (size_t)(kk + b_k0) * CHID + n0 + b_nq, 16);
        cp16(s2u(Bs + b_k1 * 136 + b_nq),
             Bbase + (size_t)(kk + b_k1) * CHID + n0 + b_nq, 16);
    };

    issue(0, 0);
    asm volatile("cp.async.commit_group;");
    issue(1, 1);
    asm volatile("cp.async.commit_group;");

    int st = 0;
    for (int it = 0; it < 16; ++it) {
        asm volatile("cp.async.wait_group 1;");
        __syncthreads();
        // refill the stage freed at the end of it-1
        if (it + 2 < 16) issue(it + 2, (st + 2) % 3);
        asm volatile("cp.async.commit_group;");

        const float* A = Abuf + st * A_ST;
        const float* B = Bbuf + st * B_ST;
        #pragma unroll
        for (int ks = 0; ks < 2; ks++) {
            const int kb = ks * 8;
            uint32_t a[2][4], b[8][2];
            #pragma unroll
            for (int mt = 0; mt < 2; mt++) {
                int mr = warp_m * 32 + mt * 16 + fr;
                a[mt][0] = f2tf(A[mr * 20 + kb + fc]);
                a[mt][1] = f2tf(A[(mr + 8) * 20 + kb + fc]);
                a[mt][2] = f2tf(A[mr * 20 + kb + fc + 4]);
                a[mt][3] = f2tf(A[(mr + 8) * 20 + kb + fc + 4]);
            }
            #pragma unroll
            for (int nt = 0; nt < 8; nt++) {
                int nc = warp_n * 64 + nt * 8 + fr;
                b[nt][0] = f2tf(B[(kb + fc) * 136 + nc]);
                b[nt][1] = f2tf(B[(kb + fc + 4) * 136 + nc]);
            }
            #pragma unroll
            for (int mt = 0; mt < 2; mt++)
                #pragma unroll
                for (int nt = 0; nt < 8; nt++)
                    mma_tf32(acc[mt][nt], a[mt], b[nt]);
        }
        st = (st + 1) % 3;
    }

    // ---- epilogue: bias + relu, write g_h ----
    #pragma unroll
    for (int mt = 0; mt < 2; mt++) {
        int gm = m0 + warp_m * 32 + mt * 16 + fr;
        #pragma unroll
        for (int nt = 0; nt < 8; nt++) {
            int gn = n0 + warp_n * 64 + nt * 8 + (fc << 1);
            float b0 = bias[gn], b1 = bias[gn + 1];
            if (gm < CN1) {
                float2 v = make_float2(fmaxf(acc[mt][nt][0] + b0, 0.f),
                                       fmaxf(acc[mt][nt][1] + b1, 0.f));
                *(float2*)(g_h + (size_t)gm * CHID + gn) = v;
            }
            if (gm + 8 < CN1) {
                float2 v = make_float2(fmaxf(acc[mt][nt][2] + b0, 0.f),
                                       fmaxf(acc[mt][nt][3] + b1, 0.f));
                *(float2*)(g_h + (size_t)(gm + 8) * CHID + gn) = v;
            }
        }
    }
}

// ---------------------------------------------------------------------------
// layer-2 fused GEMM + log_softmax. Warp per row.
// ---------------------------------------------------------------------------
__global__ void __launch_bounds__(256) k_gemm2(const float* __restrict__ wl,
                                               const float* __restrict__ wr,
                                               const float* __restrict__ bias,
                                               float* __restrict__ out) {
    __shared__ float As[8][512];
    int warp = threadIdx.x >> 5, lane = threadIdx.x & 31;
    int m = blockIdx.x * 8 + warp;
    if (m >= CN2) return;
    #pragma unroll
    for (int i = 0; i < 8; i++)
        As[warp][lane + 32 * i] = g_agg2[(size_t)m * CHID + lane + 32 * i];
    #pragma unroll
    for (int i = 0; i < 8; i++)
        As[warp][CHID + lane + 32 * i] = g_h[(size_t)m * CHID + lane + 32 * i];
    __syncwarp();

    float acc0 = 0.f, acc1 = 0.f;
    const float* A = As[warp];
    #pragma unroll 8
    for (int k = 0; k < CHID; k++) {
        float a = A[k];
        acc0 += a * wl[k * COUT + lane];
        acc1 += a * wl[k * COUT + lane + 32];
    }
    #pragma unroll 8
    for (int k = 0; k < CHID; k++) {
        float a = A[CHID + k];
        acc0 += a * wr[k * COUT + lane];
        acc1 += a * wr[k * COUT + lane + 32];
    }
    acc0 += bias[lane];
    acc1 += bias[lane + 32];

    float mx = fmaxf(acc0, acc1);
    #pragma unroll
    for (int o = 16; o > 0; o >>= 1) mx = fmaxf(mx, __shfl_xor_sync(0xFFFFFFFFu, mx, o));
    float s = expf(acc0 - mx) + expf(acc1 - mx);
    #pragma unroll
    for (int o = 16; o > 0; o >>= 1) s += __shfl_xor_sync(0xFFFFFFFFu, s, o);
    float lse = mx + logf(s);
    out[(size_t)m * COUT + lane]      = acc0 - lse;
    out[(size_t)m * COUT + lane + 32] = acc1 - lse;
}

// ---------------------------------------------------------------------------
extern "C" void kernel_launch(void* const* d_in, const int* in_sizes, int n_in,
                              void* d_out, int out_size) {
    const float* x    = (const float*)d_in[0];
    const int*   src1 = (const int*)d_in[1];
    const int*   dst1 = (const int*)d_in[2];
    const int*   src2 = (const int*)d_in[3];
    const int*   dst2 = (const int*)d_in[4];
    const float* wl1  = (const float*)d_in[5];
    const float* bl1  = (const float*)d_in[6];
    const float* wr1  = (const float*)d_in[7];
    const float* wl2  = (const float*)d_in[8];
    const float* bl2  = (const float*)d_in[9];
    const float* wr2  = (const float*)d_in[10];
    int E1 = in_sizes[1];
    int E2 = in_sizes[3];

    cudaFuncSetAttribute(k_gemm1, cudaFuncAttributeMaxDynamicSharedMemorySize,
                         SMEM_GEMM1);

    k_zero<<<(CN1 + 1023) / 1024, 1024>>>();
    k_count<<<(E1 + E2 + 255) / 256, 256>>>(dst1, dst2, E1, E2);
    k_scan_a<<<NB1 + NB2, 1024>>>();
    k_scan_b<<<1, 64>>>();
    k_scan_c<<<NB1 + NB2, 1024>>>(E1, E2);
    k_fill<<<(E1 + E2 + 255) / 256, 256>>>(src1, dst1, src2, dst2, E1, E2);
    k_gather1<<<(CN1 * 32 + 255) / 256, 256>>>(x);
    k_gemm1<<<dim3(2, (CN1 + 127) / 128), 256, SMEM_GEMM1>>>(x, wl1, wr1, bl1);
    k_gather2<<<(CN2 * 32 + 255) / 256, 256>>>();
    k_gemm2<<<(CN2 + 7) / 8, 256>>>(wl2, wr2, bl2, (float*)d_out);
}

// round 8
// speedup vs baseline: 1.3192x; 1.0035x over previous
#include <cuda_runtime.h>
#include <cstdint>

#define CN0  400000
#define CN1  40000
#define CN2  4000
#define CIN  128
#define CHID 256
#define COUT 64
#define CE1  640000
#define CE2  64000
#define NB1  40               // scan blocks layer1 (40960 >= 40000)
#define NB2  4                // scan blocks layer2 (4096 >= 4000)

// ---- scratch (device globals: no allocation allowed) ----
__device__ float g_agg1[CN1 * CIN];
__device__ float g_h   [CN1 * CHID];
__device__ float g_agg2[CN2 * CHID];
__device__ int   g_cnt1[CN1];
__device__ int   g_off1[CN1 + 1];
__device__ int   g_csr1[CE1];
__device__ int   g_cnt2[CN2];
__device__ int   g_off2[CN2 + 1];
__device__ int   g_csr2[CE2];
__device__ int   g_bsum[64];

// ---------------------------------------------------------------------------
__global__ void k_zero() {
    int i = blockIdx.x * blockDim.x + threadIdx.x;
    if (i < CN1) g_cnt1[i] = 0;
    if (i < CN2) g_cnt2[i] = 0;
}

// merged histogram for both layers
__global__ void k_count(const int* __restrict__ d1, const int* __restrict__ d2,
                        int E1, int E2) {
    int i = blockIdx.x * blockDim.x + threadIdx.x;
    if (i < E1) atomicAdd(g_cnt1 + d1[i], 1);
    else {
        int j = i - E1;
        if (j < E2) atomicAdd(g_cnt2 + d2[j], 1);
    }
}

// Phase A: per-block exclusive scan, emit block sum (blocks 0..39 L1, 40..43 L2)
__global__ void __launch_bounds__(1024) k_scan_a() {
    int b = blockIdx.x;
    int lay = (b >= NB1);
    int bb = lay ? b - NB1 : b;
    int n = lay ? CN2 : CN1;
    int* cnt = lay ? g_cnt2 : g_cnt1;
    int* off = lay ? g_off2 : g_off1;
    __shared__ int ps[1024];
    int t = threadIdx.x;
    int i = bb * 1024 + t;
    int v = (i < n) ? cnt[i] : 0;
    ps[t] = v;
    __syncthreads();
    #pragma unroll
    for (int d = 1; d < 1024; d <<= 1) {
        int u = (t >= d) ? ps[t - d] : 0;
        __syncthreads();
        ps[t] += u;
        __syncthreads();
    }
    if (i < n) off[i] = ps[t] - v;
    if (t == 1023) g_bsum[b] = ps[1023];
}

// Phase C: compute own block prefix from g_bsum, add it, reset cnt, set off[n]
__global__ void __launch_bounds__(1024) k_scan_c(int E1, int E2) {
    int b = blockIdx.x;
    int lay = (b >= NB1);
    int bb = lay ? b - NB1 : b;
    int n = lay ? CN2 : CN1;
    int segbase = lay ? NB1 : 0;
    int* cnt = lay ? g_cnt2 : g_cnt1;
    int* off = lay ? g_off2 : g_off1;
    __shared__ int add_s;
    int t = threadIdx.x;
    if (t == 0) {
        int s = 0;
        for (int j = segbase; j < b; j++) s += g_bsum[j];
        add_s = s;
    }
    __syncthreads();
    int add = add_s;
    int i = bb * 1024 + t;
    if (i < n) { off[i] += add; cnt[i] = 0; }
    if (i == 0) off[n] = lay ? E2 : E1;
}

// merged ticket fill for both layers
__global__ void k_fill(const int* __restrict__ s1, const int* __restrict__ d1,
                       const int* __restrict__ s2, const int* __restrict__ d2,
                       int E1, int E2) {
    int i = blockIdx.x * blockDim.x + threadIdx.x;
    if (i < E1) {
        int d = d1[i];
        int pos = atomicAdd(g_cnt1 + d, 1);
        g_csr1[g_off1[d] + pos] = s1[i];
    } else {
        int j = i - E1;
        if (j < E2) {
            int d = d2[j];
            int pos = atomicAdd(g_cnt2 + d, 1);
            g_csr2[g_off2[d] + pos] = s2[j];
        }
    }
}

// ---------------------------------------------------------------------------
// layer-1 gather-mean: warp per dst row, 128 floats = 32 lanes x float4
// ---------------------------------------------------------------------------
__global__ void __launch_bounds__(256) k_gather1(const float* __restrict__ x) {
    int w = (blockIdx.x * blockDim.x + threadIdx.x) >> 5;
    if (w >= CN1) return;
    int lane = threadIdx.x & 31;
    int e0 = g_off1[w], e1 = g_off1[w + 1];
    float4 acc = make_float4(0.f, 0.f, 0.f, 0.f);
    int i = e0;
    for (; i + 3 < e1; i += 4) {
        int s0 = g_csr1[i], s1 = g_csr1[i + 1], s2 = g_csr1[i + 2], s3 = g_csr1[i + 3];
        float4 v0 = ((const float4*)(x + (size_t)s0 * CIN))[lane];
        float4 v1 = ((const float4*)(x + (size_t)s1 * CIN))[lane];
        float4 v2 = ((const float4*)(x + (size_t)s2 * CIN))[lane];
        float4 v3 = ((const float4*)(x + (size_t)s3 * CIN))[lane];
        acc.x += v0.x + v1.x + v2.x + v3.x;
        acc.y += v0.y + v1.y + v2.y + v3.y;
        acc.z += v0.z + v1.z + v2.z + v3.z;
        acc.w += v0.w + v1.w + v2.w + v3.w;
    }
    for (; i < e1; i++) {
        int s = g_csr1[i];
        float4 v = ((const float4*)(x + (size_t)s * CIN))[lane];
        acc.x += v.x; acc.y += v.y; acc.z += v.z; acc.w += v.w;
    }
    float id = 1.0f / fmaxf((float)(e1 - e0), 1.0f);
    acc.x *= id; acc.y *= id; acc.z *= id; acc.w *= id;
    ((float4*)(g_agg1 + (size_t)w * CIN))[lane] = acc;
}

// ---------------------------------------------------------------------------
// layer-2 gather-mean
// ---------------------------------------------------------------------------
__global__ void __launch_bounds__(256) k_gather2() {
    int w = (blockIdx.x * blockDim.x + threadIdx.x) >> 5;
    if (w >= CN2) return;
    int lane = threadIdx.x & 31;
    int e0 = g_off2[w], e1 = g_off2[w + 1];
    float4 a0 = make_float4(0.f, 0.f, 0.f, 0.f);
    float4 a1 = a0;
    int i = e0;
    for (; i + 1 < e1; i += 2) {
        int s0 = g_csr2[i], s1 = g_csr2[i + 1];
        const float4* p0 = (const float4*)(g_h + (size_t)s0 * CHID);
        const float4* p1 = (const float4*)(g_h + (size_t)s1 * CHID);
        float4 u0 = p0[lane], u1 = p0[lane + 32];
        float4 v0 = p1[lane], v1 = p1[lane + 32];
        a0.x += u0.x + v0.x; a0.y += u0.y + v0.y; a0.z += u0.z + v0.z; a0.w += u0.w + v0.w;
        a1.x += u1.x + v1.x; a1.y += u1.y + v1.y; a1.z += u1.z + v1.z; a1.w += u1.w + v1.w;
    }
    for (; i < e1; i++) {
        const float4* p = (const float4*)(g_h + (size_t)g_csr2[i] * CHID);
        float4 u0 = p[lane], u1 = p[lane + 32];
        a0.x += u0.x; a0.y += u0.y; a0.z += u0.z; a0.w += u0.w;
        a1.x += u1.x; a1.y += u1.y; a1.z += u1.z; a1.w += u1.w;
    }
    float id = 1.0f / fmaxf((float)(e1 - e0), 1.0f);
    a0.x *= id; a0.y *= id; a0.z *= id; a0.w *= id;
    a1.x *= id; a1.y *= id; a1.z *= id; a1.w *= id;
    float4* ap = (float4*)(g_agg2 + (size_t)w * CHID);
    ap[lane] = a0;
    ap[lane + 32] = a1;
}

// ---------------------------------------------------------------------------
// tf32 helpers
// ---------------------------------------------------------------------------
__device__ __forceinline__ uint32_t f2tf(float v) {
    uint32_t r;
    asm("cvt.rna.tf32.f32 %0, %1;" : "=r"(r) : "f"(v));
    return r;
}

__device__ __forceinline__ void mma_tf32(float* c, const uint32_t* a, const uint32_t* b) {
    asm volatile(
        "mma.sync.aligned.m16n8k8.row.col.f32.tf32.tf32.f32 "
        "{%0,%1,%2,%3}, {%4,%5,%6,%7}, {%8,%9}, {%0,%1,%2,%3};"
        : "+f"(c[0]), "+f"(c[1]), "+f"(c[2]), "+f"(c[3])
        : "r"(a[0]), "r"(a[1]), "r"(a[2]), "r"(a[3]), "r"(b[0]), "r"(b[1]));
}

__device__ __forceinline__ uint32_t s2u(const void* p) {
    return (uint32_t)__cvta_generic_to_shared(p);
}

__device__ __forceinline__ void cp16(uint32_t dst, const void* src) {
    asm volatile("cp.async.cg.shared.global [%0], [%1], 16;"
                 :: "r"(dst), "l"(src));
}

// ---------------------------------------------------------------------------
// layer-1 fused GEMM (tf32, 3-stage cp.async pipeline, BM=64 x BN=256):
//   h = relu([agg1 | x_root] @ [w_l1;w_r1] + b_l1)
// M=40000 (625 blocks x 64 rows, exact), K=256 (16 iters BK=16), N=256 full.
// 256 thr, warp grid 2(m) x 4(n), warp tile 32x64.
// Each A row is read exactly once from DRAM; B (512 KB weights) is L2-resident.
// ---------------------------------------------------------------------------
#define A_ST 1280    /* 64*20 floats per stage */
#define B_ST 4224    /* 16*264 floats per stage */
#define SMEM_GEMM1 ((3 * (A_ST + B_ST)) * 4)

__global__ void __launch_bounds__(256, 2) k_gemm1(const float* __restrict__ x,
                                                  const float* __restrict__ wl,
                                                  const float* __restrict__ wr,
                                                  const float* __restrict__ bias) {
    extern __shared__ float sm[];
    float* Abuf = sm;                  // 3 stages of [64][20]
    float* Bbuf = sm + 3 * A_ST;       // 3 stages of [16][264]

    const int t = threadIdx.x;
    const int lane = t & 31, warp = t >> 5;
    const int warp_m = warp & 1;       // 0..1 -> 32-row slab
    const int warp_n = warp >> 1;      // 0..3 -> 64-col slab
    const int m0 = blockIdx.y * 64;
    const int fr = lane >> 2;          // 0..7
    const int fc = lane & 3;           // 0..3

    const int a_row = t >> 2,  a_kq = (t & 3) * 4;     // 1 float4 per thread
    const int b_nq  = (t & 63) * 4;                     // 4 float4 per thread

    float acc[2][8][4] = {};

    auto issue = [&](int it, int st) {
        const int kk = (it & 7) * 16;
        const float* Abase = (it < 8) ? g_agg1 : x;
        const float* Bbase = (it < 8) ? wl : wr;
        float* As = Abuf + st * A_ST;
        float* Bs = Bbuf + st * B_ST;
        cp16(s2u(As + a_row * 20 + a_kq),
             Abase + (size_t)(m0 + a_row) * CIN + kk + a_kq);
        #pragma unroll
        for (int i = 0; i < 4; i++) {
            int krow = (t + i * 256) >> 6;      // 0..15
            cp16(s2u(Bs + krow * 264 + b_nq),
                 Bbase + (size_t)(kk + krow) * CHID + b_nq);
        }
    };

    issue(0, 0);
    asm volatile("cp.async.commit_group;");
    issue(1, 1);
    asm volatile("cp.async.commit_group;");

    int st = 0;
    for (int it = 0; it < 16; ++it) {
        asm volatile("cp.async.wait_group 1;");
        __syncthreads();
        if (it + 2 < 16) issue(it + 2, (st + 2) % 3);
        asm volatile("cp.async.commit_group;");

        const float* A = Abuf + st * A_ST;
        const float* B = Bbuf + st * B_ST;
        #pragma unroll
        for (int ks = 0; ks < 2; ks++) {
            const int kb = ks * 8;
            uint32_t a[2][4], b[8][2];
            #pragma unroll
            for (int mt = 0; mt < 2; mt++) {
                int mr = warp_m * 32 + mt * 16 + fr;
                a[mt][0] = f2tf(A[mr * 20 + kb + fc]);
                a[mt][1] = f2tf(A[(mr + 8) * 20 + kb + fc]);
                a[mt][2] = f2tf(A[mr * 20 + kb + fc + 4]);
                a[mt][3] = f2tf(A[(mr + 8) * 20 + kb + fc + 4]);
            }
            #pragma unroll
            for (int nt = 0; nt < 8; nt++) {
                int nc = warp_n * 64 + nt * 8 + fr;
                b[nt][0] = f2tf(B[(kb + fc) * 264 + nc]);
                b[nt][1] = f2tf(B[(kb + fc + 4) * 264 + nc]);
            }
            #pragma unroll
            for (int mt = 0; mt < 2; mt++)
                #pragma unroll
                for (int nt = 0; nt < 8; nt++)
                    mma_tf32(acc[mt][nt], a[mt], b[nt]);
        }
        st = (st + 1) % 3;
    }

    // ---- epilogue: bias + relu, write g_h (no bounds needed: 625*64 == CN1) ----
    #pragma unroll
    for (int mt = 0; mt < 2; mt++) {
        int gm = m0 + warp_m * 32 + mt * 16 + fr;
        #pragma unroll
        for (int nt = 0; nt < 8; nt++) {
            int gn = warp_n * 64 + nt * 8 + (fc << 1);
            float b0 = bias[gn], b1 = bias[gn + 1];
            float2 v0 = make_float2(fmaxf(acc[mt][nt][0] + b0, 0.f),
                                    fmaxf(acc[mt][nt][1] + b1, 0.f));
            *(float2*)(g_h + (size_t)gm * CHID + gn) = v0;
            float2 v1 = make_float2(fmaxf(acc[mt][nt][2] + b0, 0.f),
                                    fmaxf(acc[mt][nt][3] + b1, 0.f));
            *(float2*)(g_h + (size_t)(gm + 8) * CHID + gn) = v1;
        }
    }
}

// ---------------------------------------------------------------------------
// layer-2 fused GEMM + log_softmax. Warp per row.
// ---------------------------------------------------------------------------
__global__ void __launch_bounds__(256) k_gemm2(const float* __restrict__ wl,
                                               const float* __restrict__ wr,
                                               const float* __restrict__ bias,
                                               float* __restrict__ out) {
    __shared__ float As[8][512];
    int warp = threadIdx.x >> 5, lane = threadIdx.x & 31;
    int m = blockIdx.x * 8 + warp;
    if (m >= CN2) return;
    #pragma unroll
    for (int i = 0; i < 8; i++)
        As[warp][lane + 32 * i] = g_agg2[(size_t)m * CHID + lane + 32 * i];
    #pragma unroll
    for (int i = 0; i < 8; i++)
        As[warp][CHID + lane + 32 * i] = g_h[(size_t)m * CHID + lane + 32 * i];
    __syncwarp();

    float acc0 = 0.f, acc1 = 0.f;
    const float* A = As[warp];
    #pragma unroll 8
    for (int k = 0; k < CHID; k++) {
        float a = A[k];
        acc0 += a * wl[k * COUT + lane];
        acc1 += a * wl[k * COUT + lane + 32];
    }
    #pragma unroll 8
    for (int k = 0; k < CHID; k++) {
        float a = A[CHID + k];
        acc0 += a * wr[k * COUT + lane];
        acc1 += a * wr[k * COUT + lane + 32];
    }
    acc0 += bias[lane];
    acc1 += bias[lane + 32];

    float mx = fmaxf(acc0, acc1);
    #pragma unroll
    for (int o = 16; o > 0; o >>= 1) mx = fmaxf(mx, __shfl_xor_sync(0xFFFFFFFFu, mx, o));
    float s = expf(acc0 - mx) + expf(acc1 - mx);
    #pragma unroll
    for (int o = 16; o > 0; o >>= 1) s += __shfl_xor_sync(0xFFFFFFFFu, s, o);
    float lse = mx + logf(s);
    out[(size_t)m * COUT + lane]      = acc0 - lse;
    out[(size_t)m * COUT + lane + 32] = acc1 - lse;
}

// ---------------------------------------------------------------------------
extern "C" void kernel_launch(void* const* d_in, const int* in_sizes, int n_in,
                              void* d_out, int out_size) {
    const float* x    = (const float*)d_in[0];
    const int*   src1 = (const int*)d_in[1];
    const int*   dst1 = (const int*)d_in[2];
    const int*   src2 = (const int*)d_in[3];
    const int*   dst2 = (const int*)d_in[4];
    const float* wl1  = (const float*)d_in[5];
    const float* bl1  = (const float*)d_in[6];
    const float* wr1  = (const float*)d_in[7];
    const float* wl2  = (const float*)d_in[8];
    const float* bl2  = (const float*)d_in[9];
    const float* wr2  = (const float*)d_in[10];
    int E1 = in_sizes[1];
    int E2 = in_sizes[3];

    cudaFuncSetAttribute(k_gemm1, cudaFuncAttributeMaxDynamicSharedMemorySize,
                         SMEM_GEMM1);

    k_zero<<<(CN1 + 1023) / 1024, 1024>>>();
    k_count<<<(E1 + E2 + 255) / 256, 256>>>(dst1, dst2, E1, E2);
    k_scan_a<<<NB1 + NB2, 1024>>>();
    k_scan_c<<<NB1 + NB2, 1024>>>(E1, E2);
    k_fill<<<(E1 + E2 + 255) / 256, 256>>>(src1, dst1, src2, dst2, E1, E2);
    k_gather1<<<(CN1 * 32 + 255) / 256, 256>>>(x);
    k_gemm1<<<dim3(1, CN1 / 64), 256, SMEM_GEMM1>>>(x, wl1, wr1, bl1);
    k_gather2<<<(CN2 * 32 + 255) / 256, 256>>>();
    k_gemm2<<<(CN2 + 7) / 8, 256>>>(wl2, wr2, bl2, (float*)d_out);
}